// round 11
// baseline (speedup 1.0000x reference)
#include <cuda_runtime.h>
#include <cuda_fp16.h>
#include <cstddef>
#include <cstdint>

// Shapes: B=64, C=32, H=8, Wd=8 -> P=2048 positions, I=16, O=32, D=32
#define B_   64
#define P_   2048
#define I_   16
#define O_   32
#define D_   32
#define OD_  1024
#define ROWU 512               // u32 words per (b,p) row of u_hat
#define EPS  1e-6f

// u_hat fp16, PERMUTED layout per (b,p) row of 512 u32 words:
//   word(o, widx) at offset (widx>>2)*128 + o*4 + (widx&3)   [u32 units]
//   widx = d/2 (word holds halves (2*widx, 2*widx+1)).
__device__ unsigned g_uhat[(size_t)B_ * P_ * ROWU];   // 256 MB
__device__ float    g_b[(size_t)B_ * P_ * O_];        // 16 MB
__device__ float    g_s1[B_ * OD_];                   // transposed [b][d*32+o]
__device__ float    g_s2[B_ * OD_];
__device__ float    g_s3[B_ * OD_];

// ---------------- packed fp32x2 helpers (sm_100+) ---------------------------
__device__ __forceinline__ unsigned long long pk2(float lo, float hi) {
    unsigned long long r;
    asm("mov.b64 %0, {%1, %2};" : "=l"(r) : "f"(lo), "f"(hi));
    return r;
}
__device__ __forceinline__ unsigned long long fma2(unsigned long long a,
                                                   unsigned long long b,
                                                   unsigned long long c) {
    unsigned long long d;
    asm("fma.rn.f32x2 %0, %1, %2, %3;" : "=l"(d) : "l"(a), "l"(b), "l"(c));
    return d;
}
__device__ __forceinline__ float2 upk2(unsigned long long v) {
    float2 r;
    asm("mov.b64 {%0, %1}, %2;" : "=f"(r.x), "=f"(r.y) : "l"(v));
    return r;
}
__device__ __forceinline__ float2 h2f(unsigned v) {
    __half2 h; *reinterpret_cast<unsigned*>(&h) = v;
    return __half22float2(h);
}
// 32-lane fp32 sum: butterfly (redux.sync.add.f32 NOT supported on sm_103)
__device__ __forceinline__ float warp_sum(float x) {
#pragma unroll
    for (int off = 16; off; off >>= 1)
        x += __shfl_xor_sync(0xffffffffu, x, off);
    return x;
}

// ---------------- K1: u_hat = x @ W  (+ zero s accumulators) ----------------
__global__ void __launch_bounds__(256) k_uhat(const float* __restrict__ x,
                                              const float* __restrict__ Wg) {
    const int p  = blockIdx.x;
    const int t  = threadIdx.x;
    const int o  = t >> 3;
    const int d0 = (t & 7) * 4;

    if (p < 64) {                       // fold k_zero in here
        int i0 = p * 256 + t;
#pragma unroll
        for (int k = 0; k < 4; k++) {
            g_s1[i0 + k * 16384] = 0.f;
            g_s2[i0 + k * 16384] = 0.f;
            g_s3[i0 + k * 16384] = 0.f;
        }
    }

    __shared__ unsigned long long sx2[B_ * I_];   // (xv,xv) per (b,i)
    for (int k = t; k < B_ * I_; k += 256) {
        int b = k >> 4, i = k & 15;
        float xv = x[(size_t)b * (P_ * I_) + (size_t)p * I_ + i];
        sx2[k] = pk2(xv, xv);
    }

    unsigned long long w01[I_], w23[I_];
    const float4* wp = reinterpret_cast<const float4*>(
        Wg + (size_t)p * (O_ * I_ * D_) + (size_t)o * (I_ * D_) + d0);
#pragma unroll
    for (int i = 0; i < I_; i++) {
        float4 wv = wp[i * (D_ / 4)];
        w01[i] = pk2(wv.x, wv.y);
        w23[i] = pk2(wv.z, wv.w);
    }

    __syncthreads();

    const int widx = (t & 7) * 2;       // d0/2
    unsigned* up = g_uhat + (size_t)p * ROWU
                 + (widx >> 2) * 128 + o * 4 + (widx & 3);
    const size_t bstride = (size_t)P_ * ROWU;
#pragma unroll 4
    for (int b = 0; b < B_; b++) {
        const unsigned long long* xb = sx2 + b * I_;
        unsigned long long a01 = 0ull, a23 = 0ull;
#pragma unroll
        for (int i = 0; i < I_; i++) {
            unsigned long long xx = xb[i];
            a01 = fma2(xx, w01[i], a01);
            a23 = fma2(xx, w23[i], a23);
        }
        float2 f01 = upk2(a01), f23 = upk2(a23);
        __half2 h01 = __floats2half2_rn(f01.x, f01.y);
        __half2 h23 = __floats2half2_rn(f23.x, f23.y);
        uint2 st;
        st.x = *reinterpret_cast<unsigned*>(&h01);
        st.y = *reinterpret_cast<unsigned*>(&h23);
        *reinterpret_cast<uint2*>(up + (size_t)b * bstride) = st;
    }
}

// ---------------- s1 = sum_p u_hat  (uint4 loads, deep unroll) ---------------
// grid (16 p-slices of 128, 64 b), 256 threads.
// Thread (half = t>>7, tw = t&127) owns uint4 #tw of row (pbase + half + 2k),
// k = 0..63.  Mapping for wpos = tw*4 + m:  q = tw>>5, o = tw&31, d = 8q + 2m.
__global__ void __launch_bounds__(256) k_s0() {
    const int b     = blockIdx.y;
    const int pbase = blockIdx.x * 128;
    const int t     = threadIdx.x;
    const int half  = t >> 7;
    const int tw    = t & 127;

    const uint4* up = reinterpret_cast<const uint4*>(
        g_uhat + ((size_t)b * P_ + pbase + half) * ROWU) + tw;
    float acc[8];
#pragma unroll
    for (int i = 0; i < 8; i++) acc[i] = 0.f;

#pragma unroll 8
    for (int k = 0; k < 64; k++) {
        uint4 v = up[(size_t)k * (2 * ROWU / 4)];
        float2 f0 = h2f(v.x), f1 = h2f(v.y), f2 = h2f(v.z), f3 = h2f(v.w);
        acc[0] += f0.x; acc[1] += f0.y;
        acc[2] += f1.x; acc[3] += f1.y;
        acc[4] += f2.x; acc[5] += f2.y;
        acc[6] += f3.x; acc[7] += f3.y;
    }

    const int q = tw >> 5, o = tw & 31;
    float* s = g_s1 + b * OD_;
#pragma unroll
    for (int m = 0; m < 4; m++) {
        int d = 8 * q + 2 * m;
        atomicAdd(&s[(d + 0) * O_ + o], acc[2 * m]);
        atomicAdd(&s[(d + 1) * O_ + o], acc[2 * m + 1]);
    }
}

// ---------------- coalesced row load: 16 u32 words --------------------------
__device__ __forceinline__ void load_row(const unsigned* __restrict__ row,
                                         int lane, unsigned (&r)[16]) {
    const uint4* p0 = reinterpret_cast<const uint4*>(row) + lane;
    uint4 a = p0[0], b4 = p0[32], c4 = p0[64], d4 = p0[96];
    r[0]=a.x;  r[1]=a.y;  r[2]=a.z;  r[3]=a.w;
    r[4]=b4.x; r[5]=b4.y; r[6]=b4.z; r[7]=b4.w;
    r[8]=c4.x; r[9]=c4.y; r[10]=c4.z; r[11]=c4.w;
    r[12]=d4.x; r[13]=d4.y; r[14]=d4.z; r[15]=d4.w;
}

// ---------------- fused routing pass ----------------------------------------
// grid (32 p-chunks of 64, 64 b), 256 threads = 8 warps, 8 p per warp, lane=o.
// v in registers; u unpacked once per STEP; softmax without max-subtraction
// (logits bounded ~|40|, exp safely in fp32 range, ratio unchanged).
__global__ void __launch_bounds__(256, 2) k_route(int pass) {
    const int b     = blockIdx.y;
    const int pbase = blockIdx.x * 64;
    const int w     = threadIdx.x >> 5;
    const int lane  = threadIdx.x & 31;

    const float* sin   = (pass == 1) ? g_s1 : g_s2;
    const float  scale = (pass == 1) ? (1.f / 32.f) : 1.f;
    float*       sout  = (pass == 1) ? g_s2 : g_s3;

    __shared__ float sacc[8][OD_];     // epilogue only

    const unsigned* rowbase = g_uhat + ((size_t)b * P_ + pbase + w * 8) * ROWU;
    unsigned r0[16], r1[16];
    load_row(rowbase, lane, r0);        // prefetch j=0 first

    float* gb = g_b + ((size_t)b * P_ + pbase + w * 8) * O_ + lane;

    // pass 2: prefetch all 8 b-logit priors upfront (coalesced across lanes)
    float bp[8];
    if (pass == 2) {
#pragma unroll
        for (int j = 0; j < 8; j++) bp[j] = gb[j * O_];
    } else {
#pragma unroll
        for (int j = 0; j < 8; j++) bp[j] = 0.f;
    }

    // v = squash(s*scale) for this lane's o, in registers
    float v[D_];
    {
        float sq = 0.f;
#pragma unroll
        for (int d = 0; d < D_; d++) {
            float sv = sin[b * OD_ + d * O_ + lane] * scale;
            v[d] = sv;
            sq = fmaf(sv, sv, sq);
        }
        float f = sq / ((1.f + sq) * (sqrtf(sq) + EPS));
#pragma unroll
        for (int d = 0; d < D_; d++) v[d] *= f;
    }

    float sreg[D_];
#pragma unroll
    for (int d = 0; d < D_; d++) sreg[d] = 0.f;

#define STEP(R, J) do {                                                        \
    float u[D_];                                                               \
    _Pragma("unroll")                                                          \
    for (int i = 0; i < 16; i++) {                                             \
        float2 f = h2f(R[i]);                                                  \
        u[2*i] = f.x; u[2*i+1] = f.y;                                          \
    }                                                                          \
    float a0 = 0.f, a1 = 0.f, a2 = 0.f, a3 = 0.f;                              \
    _Pragma("unroll")                                                          \
    for (int i = 0; i < 8; i++) {                                              \
        a0 = fmaf(u[4*i+0], v[4*i+0], a0);                                     \
        a1 = fmaf(u[4*i+1], v[4*i+1], a1);                                     \
        a2 = fmaf(u[4*i+2], v[4*i+2], a2);                                     \
        a3 = fmaf(u[4*i+3], v[4*i+3], a3);                                     \
    }                                                                          \
    float bn = bp[J] + (a0 + a1) + (a2 + a3);                                  \
    if (pass == 1) gb[(J) * O_] = bn;                                          \
    float e = __expf(bn);                 /* no max-subtract: bounded logits */ \
    float se = warp_sum(e);                                                    \
    float c = __fdividef(e, se);                                               \
    _Pragma("unroll")                                                          \
    for (int d = 0; d < D_; d++) sreg[d] = fmaf(c, u[d], sreg[d]);             \
} while (0)

#pragma unroll 1
    for (int j = 0; j < 8; j += 2) {
        load_row(rowbase + (size_t)(j + 1) * ROWU, lane, r1);
        STEP(r0, j);
        if (j < 6) load_row(rowbase + (size_t)(j + 2) * ROWU, lane, r0);
        STEP(r1, j + 1);
    }
#undef STEP

    // per-warp partials -> smem (transposed [d*32+o], conflict-free: bank=lane)
#pragma unroll
    for (int d = 0; d < D_; d++) sacc[w][d * O_ + lane] = sreg[d];
    __syncthreads();

    for (int idx = threadIdx.x; idx < OD_; idx += 256) {
        float a = 0.f;
#pragma unroll
        for (int ww = 0; ww < 8; ww++) a += sacc[ww][idx];
        atomicAdd(&sout[b * OD_ + idx], a);
    }
}

// ---------------- final squash -> output (b, o, d) --------------------------
__global__ void k_out(float* __restrict__ out) {
    const int b    = blockIdx.x;
    const int lane = threadIdx.x & 31;   // o
    const int w    = threadIdx.x >> 5;
    float s[D_], sq = 0.f;
#pragma unroll
    for (int d = 0; d < D_; d++) {
        float sv = g_s3[b * OD_ + d * O_ + lane];
        s[d] = sv;
        sq = fmaf(sv, sv, sq);
    }
    float f = sq / ((1.f + sq) * (sqrtf(sq) + EPS));
#pragma unroll
    for (int k = 0; k < 4; k++) {
        int d = w * 4 + k;
        out[b * OD_ + lane * D_ + d] = s[d] * f;
    }
}

// ---------------- launch ----------------------------------------------------
extern "C" void kernel_launch(void* const* d_in, const int* in_sizes, int n_in,
                              void* d_out, int out_size) {
    const float* x  = (const float*)d_in[0];
    const float* Wg = (const float*)d_in[1];
    if (n_in >= 2 && in_sizes[0] > in_sizes[1]) {   // robust to input order
        x  = (const float*)d_in[1];
        Wg = (const float*)d_in[0];
    }
    float* out = (float*)d_out;

    k_uhat <<<P_, 256>>>(x, Wg);           // also zeroes s1/s2/s3
    k_s0   <<<dim3(16, B_), 256>>>();
    k_route<<<dim3(32, B_), 256>>>(1);     // v1 inline, writes b1, accum s2
    k_route<<<dim3(32, B_), 256>>>(2);     // v2 inline, reads b1, accum s3
    k_out  <<<64, 256>>>(out);             // v3 = squash(s3)
}

// round 12
// speedup vs baseline: 1.0852x; 1.0852x over previous
#include <cuda_runtime.h>
#include <cuda_fp16.h>
#include <cstddef>
#include <cstdint>

// Shapes: B=64, C=32, H=8, Wd=8 -> P=2048 positions, I=16, O=32, D=32
#define B_   64
#define P_   2048
#define I_   16
#define O_   32
#define D_   32
#define OD_  1024
#define ROWU 512               // u32 words per (b,p) row of u_hat
#define EPS  1e-6f

// u_hat fp16, PERMUTED layout per (b,p) row of 512 u32 words:
//   word(o, widx) at offset (widx>>2)*128 + o*4 + (widx&3)   [u32 units]
//   widx = d/2 (word holds halves (2*widx, 2*widx+1)).
__device__ unsigned g_uhat[(size_t)B_ * P_ * ROWU];   // 256 MB
__device__ float    g_b[(size_t)B_ * P_ * O_];        // 16 MB
__device__ float    g_s1[B_ * OD_];                   // transposed [b][d*32+o]
__device__ float    g_s2[B_ * OD_];
__device__ float    g_s3[B_ * OD_];

// ---------------- packed fp32x2 helpers (sm_100+) ---------------------------
__device__ __forceinline__ unsigned long long pk2(float lo, float hi) {
    unsigned long long r;
    asm("mov.b64 %0, {%1, %2};" : "=l"(r) : "f"(lo), "f"(hi));
    return r;
}
__device__ __forceinline__ unsigned long long fma2(unsigned long long a,
                                                   unsigned long long b,
                                                   unsigned long long c) {
    unsigned long long d;
    asm("fma.rn.f32x2 %0, %1, %2, %3;" : "=l"(d) : "l"(a), "l"(b), "l"(c));
    return d;
}
__device__ __forceinline__ float2 upk2(unsigned long long v) {
    float2 r;
    asm("mov.b64 {%0, %1}, %2;" : "=f"(r.x), "=f"(r.y) : "l"(v));
    return r;
}
__device__ __forceinline__ float2 h2f(unsigned v) {
    __half2 h; *reinterpret_cast<unsigned*>(&h) = v;
    return __half22float2(h);
}
// streaming uint4 load (L2 evict-first: u_hat has no reuse across kernels)
__device__ __forceinline__ uint4 ldcs4(const uint4* p) {
    uint4 v;
    asm volatile("ld.global.cs.v4.u32 {%0,%1,%2,%3}, [%4];"
                 : "=r"(v.x), "=r"(v.y), "=r"(v.z), "=r"(v.w) : "l"(p));
    return v;
}
__device__ __forceinline__ float warp_sum(float x) {
#pragma unroll
    for (int off = 16; off; off >>= 1)
        x += __shfl_xor_sync(0xffffffffu, x, off);
    return x;
}

// ---------------- K1: u_hat = x @ W  (+ zero s accumulators) ----------------
__global__ void __launch_bounds__(256) k_uhat(const float* __restrict__ x,
                                              const float* __restrict__ Wg) {
    const int p  = blockIdx.x;
    const int t  = threadIdx.x;
    const int o  = t >> 3;
    const int d0 = (t & 7) * 4;

    if (p < 64) {                       // fold k_zero in here
        int i0 = p * 256 + t;
#pragma unroll
        for (int k = 0; k < 4; k++) {
            g_s1[i0 + k * 16384] = 0.f;
            g_s2[i0 + k * 16384] = 0.f;
            g_s3[i0 + k * 16384] = 0.f;
        }
    }

    __shared__ unsigned long long sx2[B_ * I_];   // (xv,xv) per (b,i)
    for (int k = t; k < B_ * I_; k += 256) {
        int b = k >> 4, i = k & 15;
        float xv = x[(size_t)b * (P_ * I_) + (size_t)p * I_ + i];
        sx2[k] = pk2(xv, xv);
    }

    unsigned long long w01[I_], w23[I_];
    const float4* wp = reinterpret_cast<const float4*>(
        Wg + (size_t)p * (O_ * I_ * D_) + (size_t)o * (I_ * D_) + d0);
#pragma unroll
    for (int i = 0; i < I_; i++) {
        float4 wv = wp[i * (D_ / 4)];
        w01[i] = pk2(wv.x, wv.y);
        w23[i] = pk2(wv.z, wv.w);
    }

    __syncthreads();

    const int widx = (t & 7) * 2;       // d0/2
    unsigned* up = g_uhat + (size_t)p * ROWU
                 + (widx >> 2) * 128 + o * 4 + (widx & 3);
    const size_t bstride = (size_t)P_ * ROWU;
#pragma unroll 2
    for (int b = 0; b < B_; b++) {
        const unsigned long long* xb = sx2 + b * I_;
        unsigned long long a01 = 0ull, a23 = 0ull;
#pragma unroll
        for (int i = 0; i < I_; i++) {
            unsigned long long xx = xb[i];
            a01 = fma2(xx, w01[i], a01);
            a23 = fma2(xx, w23[i], a23);
        }
        float2 f01 = upk2(a01), f23 = upk2(a23);
        __half2 h01 = __floats2half2_rn(f01.x, f01.y);
        __half2 h23 = __floats2half2_rn(f23.x, f23.y);
        uint2 st;
        st.x = *reinterpret_cast<unsigned*>(&h01);
        st.y = *reinterpret_cast<unsigned*>(&h23);
        *reinterpret_cast<uint2*>(up + (size_t)b * bstride) = st;
    }
}

// ---------------- s1 = sum_p u_hat (R8 structure + streaming loads) ---------
// grid (16 p-slices of 128, 64 b), 256 threads; thread t owns od = 4t..4t+3
// in word space: words 2t, 2t+1.
__global__ void __launch_bounds__(256) k_s0() {
    const int b     = blockIdx.y;
    const int pbase = blockIdx.x * 128;
    const int t     = threadIdx.x;

    const uint2* up = reinterpret_cast<const uint2*>(
        g_uhat + ((size_t)b * P_ + pbase) * ROWU) + t;
    float4 a = make_float4(0.f, 0.f, 0.f, 0.f);
#pragma unroll 4
    for (int p = 0; p < 128; p++) {
        uint2 v;
        asm volatile("ld.global.cs.v2.u32 {%0,%1}, [%2];"
                     : "=r"(v.x), "=r"(v.y)
                     : "l"(up + (size_t)p * (ROWU / 2)));
        float2 f0 = h2f(v.x);
        float2 f1 = h2f(v.y);
        a.x += f0.x; a.y += f0.y; a.z += f1.x; a.w += f1.y;
    }
    const int q  = t >> 6;
    const int o  = (t & 63) >> 1;
    const int d0 = (q * 4 + 2 * (t & 1)) * 2;
    float* s = g_s1 + b * OD_;
    atomicAdd(&s[(d0 + 0) * O_ + o], a.x);
    atomicAdd(&s[(d0 + 1) * O_ + o], a.y);
    atomicAdd(&s[(d0 + 2) * O_ + o], a.z);
    atomicAdd(&s[(d0 + 3) * O_ + o], a.w);
}

// ---------------- coalesced row load: 16 u32 words (streaming) --------------
__device__ __forceinline__ void load_row(const unsigned* __restrict__ row,
                                         int lane, unsigned (&r)[16]) {
    const uint4* p0 = reinterpret_cast<const uint4*>(row) + lane;
    uint4 a = ldcs4(p0), b4 = ldcs4(p0 + 32), c4 = ldcs4(p0 + 64),
          d4 = ldcs4(p0 + 96);
    r[0]=a.x;  r[1]=a.y;  r[2]=a.z;  r[3]=a.w;
    r[4]=b4.x; r[5]=b4.y; r[6]=b4.z; r[7]=b4.w;
    r[8]=c4.x; r[9]=c4.y; r[10]=c4.z; r[11]=c4.w;
    r[12]=d4.x; r[13]=d4.y; r[14]=d4.z; r[15]=d4.w;
}

// ---------------- fused routing pass ----------------------------------------
// grid (32 p-chunks of 64, 64 b), 256 threads = 8 warps, 8 p per warp, lane=o.
__global__ void __launch_bounds__(256, 2) k_route(int pass) {
    const int b     = blockIdx.y;
    const int pbase = blockIdx.x * 64;
    const int w     = threadIdx.x >> 5;
    const int lane  = threadIdx.x & 31;

    const float* sin   = (pass == 1) ? g_s1 : g_s2;
    const float  scale = (pass == 1) ? (1.f / 32.f) : 1.f;
    float*       sout  = (pass == 1) ? g_s2 : g_s3;

    __shared__ float sacc[8][OD_];     // epilogue only

    const unsigned* rowbase = g_uhat + ((size_t)b * P_ + pbase + w * 8) * ROWU;
    unsigned r0[16], r1[16];
    load_row(rowbase, lane, r0);        // prefetch j=0 first

    float* gb = g_b + ((size_t)b * P_ + pbase + w * 8) * O_ + lane;

    float bp[8];
    if (pass == 2) {
#pragma unroll
        for (int j = 0; j < 8; j++) bp[j] = gb[j * O_];
    } else {
#pragma unroll
        for (int j = 0; j < 8; j++) bp[j] = 0.f;
    }

    // v = squash(s*scale) for this lane's o, in registers
    float v[D_];
    {
        float sq = 0.f;
#pragma unroll
        for (int d = 0; d < D_; d++) {
            float sv = sin[b * OD_ + d * O_ + lane] * scale;
            v[d] = sv;
            sq = fmaf(sv, sv, sq);
        }
        float f = sq / ((1.f + sq) * (sqrtf(sq) + EPS));
#pragma unroll
        for (int d = 0; d < D_; d++) v[d] *= f;
    }

    float sreg[D_];
#pragma unroll
    for (int d = 0; d < D_; d++) sreg[d] = 0.f;

#define STEP(R, J) do {                                                        \
    float u[D_];                                                               \
    _Pragma("unroll")                                                          \
    for (int i = 0; i < 16; i++) {                                             \
        float2 f = h2f(R[i]);                                                  \
        u[2*i] = f.x; u[2*i+1] = f.y;                                          \
    }                                                                          \
    float a0 = 0.f, a1 = 0.f, a2 = 0.f, a3 = 0.f;                              \
    _Pragma("unroll")                                                          \
    for (int i = 0; i < 8; i++) {                                              \
        a0 = fmaf(u[4*i+0], v[4*i+0], a0);                                     \
        a1 = fmaf(u[4*i+1], v[4*i+1], a1);                                     \
        a2 = fmaf(u[4*i+2], v[4*i+2], a2);                                     \
        a3 = fmaf(u[4*i+3], v[4*i+3], a3);                                     \
    }                                                                          \
    float bn = bp[J] + (a0 + a1) + (a2 + a3);                                  \
    if (pass == 1) gb[(J) * O_] = bn;                                          \
    float e = __expf(bn);                 /* no max-subtract: bounded logits */ \
    float se = warp_sum(e);                                                    \
    float c = __fdividef(e, se);                                               \
    _Pragma("unroll")                                                          \
    for (int d = 0; d < D_; d++) sreg[d] = fmaf(c, u[d], sreg[d]);             \
} while (0)

#pragma unroll 1
    for (int j = 0; j < 8; j += 2) {
        load_row(rowbase + (size_t)(j + 1) * ROWU, lane, r1);
        STEP(r0, j);
        if (j < 6) load_row(rowbase + (size_t)(j + 2) * ROWU, lane, r0);
        STEP(r1, j + 1);
    }
#undef STEP

    // per-warp partials -> smem (transposed [d*32+o], conflict-free: bank=lane)
#pragma unroll
    for (int d = 0; d < D_; d++) sacc[w][d * O_ + lane] = sreg[d];
    __syncthreads();

    for (int idx = threadIdx.x; idx < OD_; idx += 256) {
        float a = 0.f;
#pragma unroll
        for (int ww = 0; ww < 8; ww++) a += sacc[ww][idx];
        atomicAdd(&sout[b * OD_ + idx], a);
    }
}

// ---------------- final squash -> output (b, o, d) --------------------------
__global__ void k_out(float* __restrict__ out) {
    const int b    = blockIdx.x;
    const int lane = threadIdx.x & 31;   // o
    const int w    = threadIdx.x >> 5;
    float s[D_], sq = 0.f;
#pragma unroll
    for (int d = 0; d < D_; d++) {
        float sv = g_s3[b * OD_ + d * O_ + lane];
        s[d] = sv;
        sq = fmaf(sv, sv, sq);
    }
    float f = sq / ((1.f + sq) * (sqrtf(sq) + EPS));
#pragma unroll
    for (int k = 0; k < 4; k++) {
        int d = w * 4 + k;
        out[b * OD_ + lane * D_ + d] = s[d] * f;
    }
}

// ---------------- launch ----------------------------------------------------
extern "C" void kernel_launch(void* const* d_in, const int* in_sizes, int n_in,
                              void* d_out, int out_size) {
    const float* x  = (const float*)d_in[0];
    const float* Wg = (const float*)d_in[1];
    if (n_in >= 2 && in_sizes[0] > in_sizes[1]) {   // robust to input order
        x  = (const float*)d_in[1];
        Wg = (const float*)d_in[0];
    }
    float* out = (float*)d_out;

    k_uhat <<<P_, 256>>>(x, Wg);           // also zeroes s1/s2/s3
    k_s0   <<<dim3(16, B_), 256>>>();
    k_route<<<dim3(32, B_), 256>>>(1);     // v1 inline, writes b1, accum s2
    k_route<<<dim3(32, B_), 256>>>(2);     // v2 inline, reads b1, accum s3
    k_out  <<<64, 256>>>(out);             // v3 = squash(s3)
}